// round 13
// baseline (speedup 1.0000x reference)
#include <cuda_runtime.h>
#include <cuda_fp16.h>
#include <cstdint>

#define D        64
#define KC       512
#define BROWS    128
#define THREADS  256
#define DELTA    8.0e-3f
#define C_OFS    16.0f

// ---------------- device globals (scratch; allocs forbidden) ----------------
// E baked into mma-B-fragment order: [iter(64)][half(2)][lane(32)] uint4
// padded by one iter so the software pipeline's tail prefetch stays in bounds
__device__ __align__(16) uint4  g_efrag[65 * 2 * 32];
__device__ __align__(16) float  g_eT[KC * D];      // fp32 codebook [k][d] (transposed)
__device__ __align__(16) float  g_enormC2[KC];     // -(||e_k||^2 + C)/2
__device__ double g_loss_sum;
__device__ int    g_counter = 0;

// ---------------- smem layout (dynamic, main) ----------------
#define S_X      0                      // 128 * 128B (fp16, swizzled)  = 16384
#define S_EN     16384                  // 512 * 4B                     = 2048
#define S_KMIN   18432                  // 128 * 4B  (also absorbs en-prefetch overread)
#define S_TOTAL  18944

__device__ __forceinline__ uint32_t smem_u32(const void* p) {
    uint32_t a;
    asm("{ .reg .u64 t; cvta.to.shared.u64 t, %1; cvt.u32.u64 %0, t; }" : "=r"(a) : "l"(p));
    return a;
}

__device__ __forceinline__ void cp_async16(uint32_t dst, const void* src) {
    asm volatile("cp.async.ca.shared.global [%0], [%1], 16;" :: "r"(dst), "l"(src));
}
__device__ __forceinline__ void cp_async_commit_wait() {
    asm volatile("cp.async.commit_group;");
    asm volatile("cp.async.wait_group 0;");
}

__device__ __forceinline__ void ldmatrix_x4(uint32_t* r, uint32_t addr) {
    asm volatile("ldmatrix.sync.aligned.m8n8.x4.shared.b16 {%0,%1,%2,%3}, [%4];"
                 : "=r"(r[0]), "=r"(r[1]), "=r"(r[2]), "=r"(r[3]) : "r"(addr));
}

__device__ __forceinline__ void mma16816(float& c0, float& c1, float& c2, float& c3,
                                         const uint32_t* a, uint32_t b0, uint32_t b1) {
    asm volatile("mma.sync.aligned.m16n8k16.row.col.f32.f16.f16.f32 "
                 "{%0,%1,%2,%3}, {%4,%5,%6,%7}, {%8,%9}, {%0,%1,%2,%3};"
                 : "+f"(c0), "+f"(c1), "+f"(c2), "+f"(c3)
                 : "r"(a[0]), "r"(a[1]), "r"(a[2]), "r"(a[3]), "r"(b0), "r"(b1));
}

// ================= fused prep: norms + fp32 transpose + B-fragment bake =================
__global__ void vq_prep_kernel(const float* __restrict__ E) {
    __shared__ float se[8][D + 1];     // [c_local][d], padded
    const int tid = threadIdx.x;
    const int c0  = blockIdx.x * 8;

    #pragma unroll
    for (int i = 0; i < 2; i++) {
        int t = i * THREADS + tid;     // 0..511
        int d = t >> 3, j = t & 7;     // E[d][c0+j]
        se[j][d] = E[d * KC + c0 + j];
    }
    __syncthreads();

    {
        int wj = tid >> 5, lane = tid & 31;
        float v = se[wj][lane];
        float u = se[wj][lane + 32];
        float s = v * v + u * u;
        #pragma unroll
        for (int o = 16; o > 0; o >>= 1) s += __shfl_xor_sync(0xffffffffu, s, o);
        if (lane == 0) g_enormC2[c0 + wj] = -0.5f * (s + C_OFS);
    }

    #pragma unroll
    for (int i = 0; i < 2; i++) {
        int t = i * THREADS + tid;
        int cl = t >> 6, d = t & 63;
        g_eT[(size_t)(c0 + cl) * D + d] = se[cl][d];
    }

    if (tid < 64) {
        int h = tid >> 5, lane = tid & 31;
        int cl = lane >> 2;
        int kd = 2 * (lane & 3);
        uint32_t r[4];
        #pragma unroll
        for (int i = 0; i < 2; i++) {
            int s = 2 * h + i;
            #pragma unroll
            for (int j = 0; j < 2; j++) {
                int d0 = s * 16 + j * 8 + kd;
                uint32_t lo = __half_as_ushort(__float2half_rn(se[cl][d0]));
                uint32_t hi = __half_as_ushort(__float2half_rn(se[cl][d0 + 1]));
                r[i * 2 + j] = lo | (hi << 16);
            }
        }
        g_efrag[(blockIdx.x * 2 + h) * 32 + lane] = make_uint4(r[0], r[1], r[2], r[3]);
    }
    if (blockIdx.x == 0 && tid == 0) g_loss_sum = 0.0;
}

// ================= main =================
__global__ __launch_bounds__(THREADS, 3)
void vq_main_kernel(const float* __restrict__ x,
                    float* __restrict__ out,
                    int writeLoss, int Nrows) {
    extern __shared__ __align__(16) char sm[];
    const uint32_t sb = smem_u32(sm);
    __shared__ float red[8];

    const int tid  = threadIdx.x;
    const int w    = tid >> 5, lane = tid & 31;
    const int m4   = lane & 3,  q8  = lane >> 2;
    const int rowBase = blockIdx.x * BROWS;

    // ---- stage norms via cp.async ----
    if (tid < 128)
        cp_async16(sb + S_EN + tid * 16, (const char*)g_enormC2 + tid * 16);
    // ---- stage X fp16 (swizzled rows of 128B) ----
    {
        const float4* xg = (const float4*)(x + (size_t)rowBase * D);
        #pragma unroll
        for (int i = 0; i < 8; i++) {
            int f = i * THREADS + tid;            // float4 id
            float4 v = xg[f];
            int row = f >> 4, seg = f & 15;
            uint32_t h0 = __half_as_ushort(__float2half_rn(v.x));
            uint32_t h1 = __half_as_ushort(__float2half_rn(v.y));
            uint32_t h2 = __half_as_ushort(__float2half_rn(v.z));
            uint32_t h3 = __half_as_ushort(__float2half_rn(v.w));
            uint2 u = make_uint2(h0 | (h1 << 16), h2 | (h3 << 16));
            *(uint2*)(sm + S_X + row * 128 + ((seg * 8) ^ ((row & 7) << 4))) = u;
        }
    }
    cp_async_commit_wait();
    __syncthreads();

    // ---- preload A fragments: one m16 tile x 4 k-steps ----
    uint32_t afr[4][4];
    const int tb0 = w * 16;
    #pragma unroll
    for (int s = 0; s < 4; s++) {
        int row = tb0 + (lane & 15);
        uint32_t off = (uint32_t)(s * 32 + (lane >> 4) * 16) ^ (uint32_t)((row & 7) << 4);
        ldmatrix_x4(afr[s], sb + S_X + row * 128 + off);
    }

    // ---- sweep 512 codes; 1-iter software pipeline on B fragments + norms;
    //      two independent 2-HMMA chains; top-2 via raw-bit umin ----
    uint32_t k1[2], k2[2];
    k1[0] = k1[1] = 0xFFFFFFFFu;
    k2[0] = k2[1] = 0xFFFFFFFFu;

    const uint4* __restrict__ fp = g_efrag + lane;
    const char* en_ptr = sm + S_EN + (size_t)(2 * m4) * 4;   // generic pointer (smem)

    uint4 u0 = __ldg(fp);
    uint4 u1 = __ldg(fp + 32);
    fp += 64;
    float2 en2 = *(const float2*)en_ptr;

    #pragma unroll 2
    for (int n0 = 0; n0 < KC; n0 += 8) {
        // prefetch next iteration (tail prefetch reads the pad iter / smem slack)
        uint4 v0 = __ldg(fp);
        uint4 v1 = __ldg(fp + 32);
        fp += 64;
        float2 enn = *(const float2*)(en_ptr + (size_t)(n0 + 8) * 4);

        const uint32_t col0 = (uint32_t)(n0 + 2 * m4), col1 = col0 + 1;

        // chain A (k-steps 0,1) seeded with norms; chain B (k-steps 2,3) seeded 0
        float a0 = en2.x, a1 = en2.y, a2 = en2.x, a3 = en2.y;
        float b0 = 0.f,   b1 = 0.f,   b2 = 0.f,   b3 = 0.f;
        mma16816(a0, a1, a2, a3, afr[0], u0.x, u0.y);
        mma16816(b0, b1, b2, b3, afr[2], u1.x, u1.y);
        mma16816(a0, a1, a2, a3, afr[1], u0.z, u0.w);
        mma16816(b0, b1, b2, b3, afr[3], u1.z, u1.w);
        a0 += b0; a1 += b1; a2 += b2; a3 += b3;

        // rowA = tb0 + q8 (a0,a1) ; rowB = rowA + 8 (a2,a3)
        uint32_t key, mx;
        key = (__float_as_uint(a0) & 0xFFFFFE00u) | col0;
        mx = umax(k1[0], key); k1[0] = umin(k1[0], key); k2[0] = umin(k2[0], mx);
        key = (__float_as_uint(a1) & 0xFFFFFE00u) | col1;
        mx = umax(k1[0], key); k1[0] = umin(k1[0], key); k2[0] = umin(k2[0], mx);
        key = (__float_as_uint(a2) & 0xFFFFFE00u) | col0;
        mx = umax(k1[1], key); k1[1] = umin(k1[1], key); k2[1] = umin(k2[1], mx);
        key = (__float_as_uint(a3) & 0xFFFFFE00u) | col1;
        mx = umax(k1[1], key); k1[1] = umin(k1[1], key); k2[1] = umin(k2[1], mx);

        u0 = v0; u1 = v1; en2 = enn;
    }

    // ---- merge top-2 across the 4 lanes sharing each row ----
    #pragma unroll
    for (int i = 0; i < 2; i++) {
        #pragma unroll
        for (int off = 1; off <= 2; off <<= 1) {
            uint32_t o1 = __shfl_xor_sync(0xffffffffu, k1[i], off);
            uint32_t o2 = __shfl_xor_sync(0xffffffffu, k2[i], off);
            uint32_t mx = umax(k1[i], o1);
            k1[i] = umin(k1[i], o1);
            k2[i] = umin(umin(k2[i], o2), mx);
        }
    }

    // ---- finalize rows: certified refinement on narrow gaps ----
    int* skm = (int*)(sm + S_KMIN);
    if (m4 == 0) {
        const float* en = (const float*)(sm + S_EN);
        #pragma unroll
        for (int i = 0; i < 2; i++) {
            int row = tb0 + q8 + i * 8;
            int c1 = (int)(k1[i] & 511u), c2 = (int)(k2[i] & 511u);
            float f1 = __uint_as_float(k1[i] & 0xFFFFFE00u);   // best (largest a)
            float f2 = __uint_as_float(k2[i] & 0xFFFFFE00u);
            int kmin = c1;
            if (2.f * (f1 - f2) < DELTA) {
                const float* xr = x + (size_t)(rowBase + row) * D;
                const float* e1 = g_eT + c1 * D;
                const float* e2 = g_eT + c2 * D;
                float p0 = 0.f, p1 = 0.f, p2 = 0.f, p3 = 0.f;
                float r0 = 0.f, r1 = 0.f, r2 = 0.f, r3 = 0.f;
                #pragma unroll
                for (int d = 0; d < D; d += 4) {
                    float x0 = xr[d], x1 = xr[d+1], x2 = xr[d+2], x3 = xr[d+3];
                    p0 = fmaf(x0, e1[d],   p0); p1 = fmaf(x1, e1[d+1], p1);
                    p2 = fmaf(x2, e1[d+2], p2); p3 = fmaf(x3, e1[d+3], p3);
                    r0 = fmaf(x0, e2[d],   r0); r1 = fmaf(x1, e2[d+1], r1);
                    r2 = fmaf(x2, e2[d+2], r2); r3 = fmaf(x3, e2[d+3], r3);
                }
                float s1 = -2.f * (((p0 + p1) + (p2 + p3)) + en[c1]);
                float s2 = -2.f * (((r0 + r1) + (r2 + r3)) + en[c2]);
                if (s2 < s1 || (s2 == s1 && c2 < c1)) kmin = c2;
            }
            skm[row] = kmin;
        }
    }
    __syncthreads();

    // ---- epilogue: coalesced straight-through output + loss (exact fp32 q) ----
    float lsum = 0.f;
    const float* xg = x   + (size_t)rowBase * D;
    float*       og = out + (size_t)rowBase * D;
    #pragma unroll 4
    for (int j = 0; j < (BROWS * D) / THREADS; j++) {
        int idx = j * THREADS + tid;
        int r = idx >> 6, d = idx & 63;
        float q  = g_eT[skm[r] * D + d];
        float xv = xg[idx];
        float t = q - xv;
        og[idx] = xv + t;
        lsum = fmaf(t, t, lsum);
    }
    #pragma unroll
    for (int o = 16; o > 0; o >>= 1) lsum += __shfl_xor_sync(0xffffffffu, lsum, o);
    if (lane == 0) red[w] = lsum;
    __syncthreads();
    if (tid == 0) {
        float s = 0.f;
        #pragma unroll
        for (int i = 0; i < 8; i++) s += red[i];
        atomicAdd(&g_loss_sum, (double)s);
        __threadfence();
        int old = atomicAdd(&g_counter, 1);
        if (old == (int)gridDim.x - 1) {
            g_counter = 0;
            double l = atomicAdd(&g_loss_sum, 0.0);   // coherent read of final sum
            if (writeLoss)
                out[(size_t)Nrows * D] = (float)(2.0 * l / ((double)Nrows * (double)D));
        }
    }
}

extern "C" void kernel_launch(void* const* d_in, const int* in_sizes, int n_in,
                              void* d_out, int out_size) {
    const float* x = (const float*)d_in[0];
    const float* E = (const float*)d_in[1];
    float* out = (float*)d_out;
    const int N = in_sizes[0] / D;

    cudaFuncSetAttribute(vq_main_kernel, cudaFuncAttributeMaxDynamicSharedMemorySize, S_TOTAL);

    vq_prep_kernel<<<64, THREADS>>>(E);
    vq_main_kernel<<<N / BROWS, THREADS, S_TOTAL>>>(x, out, out_size > N * D ? 1 : 0, N);
}

// round 14
// speedup vs baseline: 1.2555x; 1.2555x over previous
#include <cuda_runtime.h>
#include <cuda_fp16.h>
#include <cstdint>

#define D        64
#define KC       512
#define BROWS    128
#define THREADS  256
#define DELTA    8.0e-3f
#define C_OFS    16.0f

// ---------------- device globals (scratch; allocs forbidden) ----------------
// E baked into mma-B-fragment order: [iter(64)][half(2)][lane(32)] uint4
__device__ __align__(16) uint4  g_efrag[64 * 2 * 32];
__device__ __align__(16) float  g_eT[KC * D];      // fp32 codebook [k][d] (transposed)
__device__ __align__(16) float  g_enormC2[KC];     // -(||e_k||^2 + C)/2
__device__ double g_loss_sum;
__device__ int    g_counter = 0;

// ---------------- smem layout (dynamic, main) ----------------
#define S_X      0                      // 128 * 128B (fp16, swizzled)  = 16384
#define S_EN     16384                  // 512 * 4B                     = 2048
#define S_KM     18432                  // 128 rows * 2 halves * 8B     = 2048
#define S_KMIN   20480                  // 128 * 4B                     = 512
#define S_TOTAL  20992

__device__ __forceinline__ uint32_t smem_u32(const void* p) {
    uint32_t a;
    asm("{ .reg .u64 t; cvta.to.shared.u64 t, %1; cvt.u32.u64 %0, t; }" : "=r"(a) : "l"(p));
    return a;
}

__device__ __forceinline__ void cp_async16(uint32_t dst, const void* src) {
    asm volatile("cp.async.ca.shared.global [%0], [%1], 16;" :: "r"(dst), "l"(src));
}
__device__ __forceinline__ void cp_async_commit_wait() {
    asm volatile("cp.async.commit_group;");
    asm volatile("cp.async.wait_group 0;");
}

__device__ __forceinline__ void ldmatrix_x4(uint32_t* r, uint32_t addr) {
    asm volatile("ldmatrix.sync.aligned.m8n8.x4.shared.b16 {%0,%1,%2,%3}, [%4];"
                 : "=r"(r[0]), "=r"(r[1]), "=r"(r[2]), "=r"(r[3]) : "r"(addr));
}

__device__ __forceinline__ void mma16816(float& c0, float& c1, float& c2, float& c3,
                                         const uint32_t* a, uint32_t b0, uint32_t b1) {
    asm volatile("mma.sync.aligned.m16n8k16.row.col.f32.f16.f16.f32 "
                 "{%0,%1,%2,%3}, {%4,%5,%6,%7}, {%8,%9}, {%0,%1,%2,%3};"
                 : "+f"(c0), "+f"(c1), "+f"(c2), "+f"(c3)
                 : "r"(a[0]), "r"(a[1]), "r"(a[2]), "r"(a[3]), "r"(b0), "r"(b1));
}

// ================= fused prep: norms + fp32 transpose + B-fragment bake =================
__global__ void vq_prep_kernel(const float* __restrict__ E) {
    __shared__ float se[8][D + 1];     // [c_local][d], padded
    const int tid = threadIdx.x;
    const int c0  = blockIdx.x * 8;

    #pragma unroll
    for (int i = 0; i < 2; i++) {
        int t = i * THREADS + tid;     // 0..511
        int d = t >> 3, j = t & 7;     // E[d][c0+j]
        se[j][d] = E[d * KC + c0 + j];
    }
    __syncthreads();

    {
        int wj = tid >> 5, lane = tid & 31;
        float v = se[wj][lane];
        float u = se[wj][lane + 32];
        float s = v * v + u * u;
        #pragma unroll
        for (int o = 16; o > 0; o >>= 1) s += __shfl_xor_sync(0xffffffffu, s, o);
        if (lane == 0) g_enormC2[c0 + wj] = -0.5f * (s + C_OFS);
    }

    #pragma unroll
    for (int i = 0; i < 2; i++) {
        int t = i * THREADS + tid;
        int cl = t >> 6, d = t & 63;
        g_eT[(size_t)(c0 + cl) * D + d] = se[cl][d];
    }

    if (tid < 64) {
        int h = tid >> 5, lane = tid & 31;
        int cl = lane >> 2;
        int kd = 2 * (lane & 3);
        uint32_t r[4];
        #pragma unroll
        for (int i = 0; i < 2; i++) {
            int s = 2 * h + i;
            #pragma unroll
            for (int j = 0; j < 2; j++) {
                int d0 = s * 16 + j * 8 + kd;
                uint32_t lo = __half_as_ushort(__float2half_rn(se[cl][d0]));
                uint32_t hi = __half_as_ushort(__float2half_rn(se[cl][d0 + 1]));
                r[i * 2 + j] = lo | (hi << 16);
            }
        }
        g_efrag[(blockIdx.x * 2 + h) * 32 + lane] = make_uint4(r[0], r[1], r[2], r[3]);
    }
    if (blockIdx.x == 0 && tid == 0) g_loss_sum = 0.0;
}

// ================= main: split-K, M=32/warp =================
__global__ __launch_bounds__(THREADS, 3)
void vq_main_kernel(const float* __restrict__ x,
                    float* __restrict__ out,
                    int writeLoss, int Nrows) {
    extern __shared__ __align__(16) char sm[];
    const uint32_t sb = smem_u32(sm);
    __shared__ float red[8];

    const int tid  = threadIdx.x;
    const int w    = tid >> 5, lane = tid & 31;
    const int m4   = lane & 3,  q8  = lane >> 2;
    const int wr   = w & 3;            // row-group 0..3
    const int ch   = w >> 2;           // code half 0..1
    const int rowBase = blockIdx.x * BROWS;

    // ---- stage norms via cp.async ----
    if (tid < 128)
        cp_async16(sb + S_EN + tid * 16, (const char*)g_enormC2 + tid * 16);
    // ---- stage X fp16 (swizzled rows of 128B) ----
    {
        const float4* xg = (const float4*)(x + (size_t)rowBase * D);
        #pragma unroll
        for (int i = 0; i < 8; i++) {
            int f = i * THREADS + tid;            // float4 id
            float4 v = xg[f];
            int row = f >> 4, seg = f & 15;
            uint32_t h0 = __half_as_ushort(__float2half_rn(v.x));
            uint32_t h1 = __half_as_ushort(__float2half_rn(v.y));
            uint32_t h2 = __half_as_ushort(__float2half_rn(v.z));
            uint32_t h3 = __half_as_ushort(__float2half_rn(v.w));
            uint2 u = make_uint2(h0 | (h1 << 16), h2 | (h3 << 16));
            *(uint2*)(sm + S_X + row * 128 + ((seg * 8) ^ ((row & 7) << 4))) = u;
        }
    }
    cp_async_commit_wait();
    __syncthreads();

    // ---- preload A fragments: 2 m16 tiles x 4 k-steps (rows wr*32 .. wr*32+31) ----
    uint32_t afr[2][4][4];
    const int tb0 = wr * 32;
    #pragma unroll
    for (int t2 = 0; t2 < 2; t2++) {
        #pragma unroll
        for (int s = 0; s < 4; s++) {
            int row = tb0 + t2 * 16 + (lane & 15);
            uint32_t off = (uint32_t)(s * 32 + (lane >> 4) * 16) ^ (uint32_t)((row & 7) << 4);
            ldmatrix_x4(afr[t2][s], sb + S_X + row * 128 + off);
        }
    }

    // ---- sweep 256 codes (this warp's half); each B load feeds two
    //      independent 4-HMMA chains (tile0 / tile1); top-2 via raw-bit umin ----
    uint32_t k1[4], k2[4];
    #pragma unroll
    for (int i = 0; i < 4; i++) { k1[i] = 0xFFFFFFFFu; k2[i] = 0xFFFFFFFFu; }

    const uint4* __restrict__ fp = g_efrag + ch * 2048 + lane;  // half-1 starts at iter 32
    const int cbase = ch * 256 + 2 * m4;

    #pragma unroll 2
    for (int n0 = 0; n0 < 256; n0 += 8) {
        uint4 u0 = __ldg(fp);
        uint4 u1 = __ldg(fp + 32);
        fp += 64;

        float2 en2 = *(const float2*)(sm + S_EN + (size_t)(cbase + n0) * 4);
        const uint32_t col0 = (uint32_t)(cbase + n0), col1 = col0 + 1;

        // tile0 chain
        float a0 = en2.x, a1 = en2.y, a2 = en2.x, a3 = en2.y;
        // tile1 chain (independent)
        float b0 = en2.x, b1 = en2.y, b2 = en2.x, b3 = en2.y;
        mma16816(a0, a1, a2, a3, afr[0][0], u0.x, u0.y);
        mma16816(b0, b1, b2, b3, afr[1][0], u0.x, u0.y);
        mma16816(a0, a1, a2, a3, afr[0][1], u0.z, u0.w);
        mma16816(b0, b1, b2, b3, afr[1][1], u0.z, u0.w);
        mma16816(a0, a1, a2, a3, afr[0][2], u1.x, u1.y);
        mma16816(b0, b1, b2, b3, afr[1][2], u1.x, u1.y);
        mma16816(a0, a1, a2, a3, afr[0][3], u1.z, u1.w);
        mma16816(b0, b1, b2, b3, afr[1][3], u1.z, u1.w);

        // k index i covers row tb0 + i*8 + q8
        uint32_t key, mx;
        key = (__float_as_uint(a0) & 0xFFFFFE00u) | col0;
        mx = umax(k1[0], key); k1[0] = umin(k1[0], key); k2[0] = umin(k2[0], mx);
        key = (__float_as_uint(a1) & 0xFFFFFE00u) | col1;
        mx = umax(k1[0], key); k1[0] = umin(k1[0], key); k2[0] = umin(k2[0], mx);
        key = (__float_as_uint(a2) & 0xFFFFFE00u) | col0;
        mx = umax(k1[1], key); k1[1] = umin(k1[1], key); k2[1] = umin(k2[1], mx);
        key = (__float_as_uint(a3) & 0xFFFFFE00u) | col1;
        mx = umax(k1[1], key); k1[1] = umin(k1[1], key); k2[1] = umin(k2[1], mx);
        key = (__float_as_uint(b0) & 0xFFFFFE00u) | col0;
        mx = umax(k1[2], key); k1[2] = umin(k1[2], key); k2[2] = umin(k2[2], mx);
        key = (__float_as_uint(b1) & 0xFFFFFE00u) | col1;
        mx = umax(k1[2], key); k1[2] = umin(k1[2], key); k2[2] = umin(k2[2], mx);
        key = (__float_as_uint(b2) & 0xFFFFFE00u) | col0;
        mx = umax(k1[3], key); k1[3] = umin(k1[3], key); k2[3] = umin(k2[3], mx);
        key = (__float_as_uint(b3) & 0xFFFFFE00u) | col1;
        mx = umax(k1[3], key); k1[3] = umin(k1[3], key); k2[3] = umin(k2[3], mx);
    }

    // ---- merge top-2 across the 4 lanes sharing each row; publish per half ----
    // i -> row tb0 + [0,8,16,24][i] + q8   (i<2: tile0; i>=2: tile1)
    #pragma unroll
    for (int i = 0; i < 4; i++) {
        #pragma unroll
        for (int off = 1; off <= 2; off <<= 1) {
            uint32_t o1 = __shfl_xor_sync(0xffffffffu, k1[i], off);
            uint32_t o2 = __shfl_xor_sync(0xffffffffu, k2[i], off);
            uint32_t mx = umax(k1[i], o1);
            k1[i] = umin(k1[i], o1);
            k2[i] = umin(umin(k2[i], o2), mx);
        }
    }
    if (m4 == 0) {
        uint2* km = (uint2*)(sm + S_KM);
        #pragma unroll
        for (int i = 0; i < 4; i++) {
            int row = tb0 + ((i & 1) * 8) + ((i >> 1) * 16) + q8;
            km[row * 2 + ch] = make_uint2(k1[i], k2[i]);
        }
    }
    __syncthreads();

    // ---- per-row: merge halves, certified refinement on narrow gaps ----
    int* skm = (int*)(sm + S_KMIN);
    if (tid < BROWS) {
        const uint2* km = (const uint2*)(sm + S_KM);
        uint2 h0 = km[tid * 2 + 0];
        uint2 h1 = km[tid * 2 + 1];
        uint32_t m1 = umin(h0.x, h1.x);
        uint32_t m2 = umin(umax(h0.x, h1.x), umin(h0.y, h1.y));
        int c1 = (int)(m1 & 511u), c2 = (int)(m2 & 511u);
        float f1 = __uint_as_float(m1 & 0xFFFFFE00u);   // best (largest a)
        float f2 = __uint_as_float(m2 & 0xFFFFFE00u);
        int kmin = c1;
        if (2.f * (f1 - f2) < DELTA) {
            const float* en = (const float*)(sm + S_EN);
            const float* xr = x + (size_t)(rowBase + tid) * D;
            const float* e1 = g_eT + c1 * D;
            const float* e2 = g_eT + c2 * D;
            float p0 = 0.f, p1 = 0.f, p2 = 0.f, p3 = 0.f;
            float r0 = 0.f, r1 = 0.f, r2 = 0.f, r3 = 0.f;
            #pragma unroll
            for (int d = 0; d < D; d += 4) {
                float x0 = xr[d], x1 = xr[d+1], x2 = xr[d+2], x3 = xr[d+3];
                p0 = fmaf(x0, e1[d],   p0); p1 = fmaf(x1, e1[d+1], p1);
                p2 = fmaf(x2, e1[d+2], p2); p3 = fmaf(x3, e1[d+3], p3);
                r0 = fmaf(x0, e2[d],   r0); r1 = fmaf(x1, e2[d+1], r1);
                r2 = fmaf(x2, e2[d+2], r2); r3 = fmaf(x3, e2[d+3], r3);
            }
            float s1 = -2.f * (((p0 + p1) + (p2 + p3)) + en[c1]);
            float s2 = -2.f * (((r0 + r1) + (r2 + r3)) + en[c2]);
            if (s2 < s1 || (s2 == s1 && c2 < c1)) kmin = c2;
        }
        skm[tid] = kmin;
    }
    __syncthreads();

    // ---- epilogue: coalesced straight-through output + loss (exact fp32 q) ----
    float lsum = 0.f;
    const float* xg = x   + (size_t)rowBase * D;
    float*       og = out + (size_t)rowBase * D;
    #pragma unroll 4
    for (int j = 0; j < (BROWS * D) / THREADS; j++) {
        int idx = j * THREADS + tid;
        int r = idx >> 6, d = idx & 63;
        float q  = g_eT[skm[r] * D + d];
        float xv = xg[idx];
        float t = q - xv;
        og[idx] = xv + t;
        lsum = fmaf(t, t, lsum);
    }
    #pragma unroll
    for (int o = 16; o > 0; o >>= 1) lsum += __shfl_xor_sync(0xffffffffu, lsum, o);
    if (lane == 0) red[w] = lsum;
    __syncthreads();
    if (tid == 0) {
        float s = 0.f;
        #pragma unroll
        for (int i = 0; i < 8; i++) s += red[i];
        atomicAdd(&g_loss_sum, (double)s);
        __threadfence();
        int old = atomicAdd(&g_counter, 1);
        if (old == (int)gridDim.x - 1) {
            g_counter = 0;
            double l = atomicAdd(&g_loss_sum, 0.0);   // coherent read of final sum
            if (writeLoss)
                out[(size_t)Nrows * D] = (float)(2.0 * l / ((double)Nrows * (double)D));
        }
    }
}

extern "C" void kernel_launch(void* const* d_in, const int* in_sizes, int n_in,
                              void* d_out, int out_size) {
    const float* x = (const float*)d_in[0];
    const float* E = (const float*)d_in[1];
    float* out = (float*)d_out;
    const int N = in_sizes[0] / D;

    cudaFuncSetAttribute(vq_main_kernel, cudaFuncAttributeMaxDynamicSharedMemorySize, S_TOTAL);

    vq_prep_kernel<<<64, THREADS>>>(E);
    vq_main_kernel<<<N / BROWS, THREADS, S_TOTAL>>>(x, out, out_size > N * D ? 1 : 0, N);
}

// round 15
// speedup vs baseline: 1.3252x; 1.0555x over previous
#include <cuda_runtime.h>
#include <cuda_fp16.h>
#include <cstdint>

#define D        64
#define KC       512
#define BROWS    64
#define TM       128          // main-kernel threads (4 warps x 16 rows)
#define THREADS  256          // prep-kernel threads
#define DELTA    8.0e-3f
#define C_OFS    16.0f

// ---------------- device globals (scratch; allocs forbidden) ----------------
// E baked into mma-B-fragment order: [iter(64)][half(2)][lane(32)] uint4
__device__ __align__(16) uint4  g_efrag[64 * 2 * 32];
__device__ __align__(16) float  g_eT[KC * D];      // fp32 codebook [k][d] (transposed)
__device__ __align__(16) float  g_enormC2[KC];     // -(||e_k||^2 + C)/2
__device__ double g_loss_sum;
__device__ int    g_counter = 0;

// ---------------- smem layout (dynamic, main) ----------------
#define S_X      0                      // 64 * 128B (fp16, swizzled)   = 8192
#define S_EN     8192                   // 512 * 4B                     = 2048
#define S_KMIN   10240                  // 64 * 4B                      = 256
#define S_TOTAL  10496

__device__ __forceinline__ uint32_t smem_u32(const void* p) {
    uint32_t a;
    asm("{ .reg .u64 t; cvta.to.shared.u64 t, %1; cvt.u32.u64 %0, t; }" : "=r"(a) : "l"(p));
    return a;
}

__device__ __forceinline__ void cp_async16(uint32_t dst, const void* src) {
    asm volatile("cp.async.ca.shared.global [%0], [%1], 16;" :: "r"(dst), "l"(src));
}
__device__ __forceinline__ void cp_async_commit_wait() {
    asm volatile("cp.async.commit_group;");
    asm volatile("cp.async.wait_group 0;");
}

__device__ __forceinline__ void ldmatrix_x4(uint32_t* r, uint32_t addr) {
    asm volatile("ldmatrix.sync.aligned.m8n8.x4.shared.b16 {%0,%1,%2,%3}, [%4];"
                 : "=r"(r[0]), "=r"(r[1]), "=r"(r[2]), "=r"(r[3]) : "r"(addr));
}

__device__ __forceinline__ void mma16816(float& c0, float& c1, float& c2, float& c3,
                                         const uint32_t* a, uint32_t b0, uint32_t b1) {
    asm volatile("mma.sync.aligned.m16n8k16.row.col.f32.f16.f16.f32 "
                 "{%0,%1,%2,%3}, {%4,%5,%6,%7}, {%8,%9}, {%0,%1,%2,%3};"
                 : "+f"(c0), "+f"(c1), "+f"(c2), "+f"(c3)
                 : "r"(a[0]), "r"(a[1]), "r"(a[2]), "r"(a[3]), "r"(b0), "r"(b1));
}

// ================= fused prep: norms + fp32 transpose + B-fragment bake =================
__global__ void vq_prep_kernel(const float* __restrict__ E) {
    __shared__ float se[8][D + 1];     // [c_local][d], padded
    const int tid = threadIdx.x;
    const int c0  = blockIdx.x * 8;

    #pragma unroll
    for (int i = 0; i < 2; i++) {
        int t = i * THREADS + tid;     // 0..511
        int d = t >> 3, j = t & 7;     // E[d][c0+j]
        se[j][d] = E[d * KC + c0 + j];
    }
    __syncthreads();

    {
        int wj = tid >> 5, lane = tid & 31;
        float v = se[wj][lane];
        float u = se[wj][lane + 32];
        float s = v * v + u * u;
        #pragma unroll
        for (int o = 16; o > 0; o >>= 1) s += __shfl_xor_sync(0xffffffffu, s, o);
        if (lane == 0) g_enormC2[c0 + wj] = -0.5f * (s + C_OFS);
    }

    #pragma unroll
    for (int i = 0; i < 2; i++) {
        int t = i * THREADS + tid;
        int cl = t >> 6, d = t & 63;
        g_eT[(size_t)(c0 + cl) * D + d] = se[cl][d];
    }

    if (tid < 64) {
        int h = tid >> 5, lane = tid & 31;
        int cl = lane >> 2;
        int kd = 2 * (lane & 3);
        uint32_t r[4];
        #pragma unroll
        for (int i = 0; i < 2; i++) {
            int s = 2 * h + i;
            #pragma unroll
            for (int j = 0; j < 2; j++) {
                int d0 = s * 16 + j * 8 + kd;
                uint32_t lo = __half_as_ushort(__float2half_rn(se[cl][d0]));
                uint32_t hi = __half_as_ushort(__float2half_rn(se[cl][d0 + 1]));
                r[i * 2 + j] = lo | (hi << 16);
            }
        }
        g_efrag[(blockIdx.x * 2 + h) * 32 + lane] = make_uint4(r[0], r[1], r[2], r[3]);
    }
    if (blockIdx.x == 0 && tid == 0) g_loss_sum = 0.0;
}

// ================= main: 64-row tiles, 4 warps, 8 blocks/SM =================
__global__ __launch_bounds__(TM, 8)
void vq_main_kernel(const float* __restrict__ x,
                    float* __restrict__ out,
                    int writeLoss, int Nrows) {
    extern __shared__ __align__(16) char sm[];
    const uint32_t sb = smem_u32(sm);
    __shared__ float red[4];

    const int tid  = threadIdx.x;
    const int w    = tid >> 5, lane = tid & 31;
    const int m4   = lane & 3,  q8  = lane >> 2;
    const int rowBase = blockIdx.x * BROWS;

    // ---- stage norms via cp.async (128 threads x 16B = 2048B) ----
    cp_async16(sb + S_EN + tid * 16, (const char*)g_enormC2 + tid * 16);
    // ---- stage X fp16 (swizzled rows of 128B) ----
    {
        const float4* xg = (const float4*)(x + (size_t)rowBase * D);
        #pragma unroll
        for (int i = 0; i < 8; i++) {
            int f = i * TM + tid;                 // float4 id, 0..1023
            float4 v = xg[f];
            int row = f >> 4, seg = f & 15;
            uint32_t h0 = __half_as_ushort(__float2half_rn(v.x));
            uint32_t h1 = __half_as_ushort(__float2half_rn(v.y));
            uint32_t h2 = __half_as_ushort(__float2half_rn(v.z));
            uint32_t h3 = __half_as_ushort(__float2half_rn(v.w));
            uint2 u = make_uint2(h0 | (h1 << 16), h2 | (h3 << 16));
            *(uint2*)(sm + S_X + row * 128 + ((seg * 8) ^ ((row & 7) << 4))) = u;
        }
    }
    cp_async_commit_wait();
    __syncthreads();

    // ---- preload A fragments: one m16 tile x 4 k-steps ----
    uint32_t afr[4][4];
    const int tb0 = w * 16;
    #pragma unroll
    for (int s = 0; s < 4; s++) {
        int row = tb0 + (lane & 15);
        uint32_t off = (uint32_t)(s * 32 + (lane >> 4) * 16) ^ (uint32_t)((row & 7) << 4);
        ldmatrix_x4(afr[s], sb + S_X + row * 128 + off);
    }

    // ---- sweep 512 codes; B fragments from L1-cached global; top-2 via
    //      raw-bit umin (a < 0 always => min score = min uint bits) ----
    uint32_t k1[2], k2[2];
    k1[0] = k1[1] = 0xFFFFFFFFu;
    k2[0] = k2[1] = 0xFFFFFFFFu;

    const uint4* __restrict__ fp = g_efrag + lane;

    #pragma unroll 4
    for (int n0 = 0; n0 < KC; n0 += 8) {
        uint4 u0 = __ldg(fp);
        uint4 u1 = __ldg(fp + 32);
        fp += 64;

        float2 en2 = *(const float2*)(sm + S_EN + (n0 + 2 * m4) * 4);
        const uint32_t col0 = (uint32_t)(n0 + 2 * m4), col1 = col0 + 1;

        float a0 = en2.x, a1 = en2.y, a2 = en2.x, a3 = en2.y;
        mma16816(a0, a1, a2, a3, afr[0], u0.x, u0.y);
        mma16816(a0, a1, a2, a3, afr[1], u0.z, u0.w);
        mma16816(a0, a1, a2, a3, afr[2], u1.x, u1.y);
        mma16816(a0, a1, a2, a3, afr[3], u1.z, u1.w);

        // rowA = tb0 + q8 (a0,a1) ; rowB = rowA + 8 (a2,a3)
        uint32_t key, mx;
        key = (__float_as_uint(a0) & 0xFFFFFE00u) | col0;
        mx = umax(k1[0], key); k1[0] = umin(k1[0], key); k2[0] = umin(k2[0], mx);
        key = (__float_as_uint(a1) & 0xFFFFFE00u) | col1;
        mx = umax(k1[0], key); k1[0] = umin(k1[0], key); k2[0] = umin(k2[0], mx);
        key = (__float_as_uint(a2) & 0xFFFFFE00u) | col0;
        mx = umax(k1[1], key); k1[1] = umin(k1[1], key); k2[1] = umin(k2[1], mx);
        key = (__float_as_uint(a3) & 0xFFFFFE00u) | col1;
        mx = umax(k1[1], key); k1[1] = umin(k1[1], key); k2[1] = umin(k2[1], mx);
    }

    // ---- merge top-2 across the 4 lanes sharing each row ----
    #pragma unroll
    for (int i = 0; i < 2; i++) {
        #pragma unroll
        for (int off = 1; off <= 2; off <<= 1) {
            uint32_t o1 = __shfl_xor_sync(0xffffffffu, k1[i], off);
            uint32_t o2 = __shfl_xor_sync(0xffffffffu, k2[i], off);
            uint32_t mx = umax(k1[i], o1);
            k1[i] = umin(k1[i], o1);
            k2[i] = umin(umin(k2[i], o2), mx);
        }
    }

    // ---- finalize rows: certified refinement on narrow gaps ----
    int* skm = (int*)(sm + S_KMIN);
    if (m4 == 0) {
        const float* en = (const float*)(sm + S_EN);
        #pragma unroll
        for (int i = 0; i < 2; i++) {
            int row = tb0 + q8 + i * 8;
            int c1 = (int)(k1[i] & 511u), c2 = (int)(k2[i] & 511u);
            float f1 = __uint_as_float(k1[i] & 0xFFFFFE00u);   // best (largest a)
            float f2 = __uint_as_float(k2[i] & 0xFFFFFE00u);
            int kmin = c1;
            if (2.f * (f1 - f2) < DELTA) {
                const float* xr = x + (size_t)(rowBase + row) * D;
                const float* e1 = g_eT + c1 * D;
                const float* e2 = g_eT + c2 * D;
                float p0 = 0.f, p1 = 0.f, p2 = 0.f, p3 = 0.f;
                float r0 = 0.f, r1 = 0.f, r2 = 0.f, r3 = 0.f;
                #pragma unroll
                for (int d = 0; d < D; d += 4) {
                    float x0 = xr[d], x1 = xr[d+1], x2 = xr[d+2], x3 = xr[d+3];
                    p0 = fmaf(x0, e1[d],   p0); p1 = fmaf(x1, e1[d+1], p1);
                    p2 = fmaf(x2, e1[d+2], p2); p3 = fmaf(x3, e1[d+3], p3);
                    r0 = fmaf(x0, e2[d],   r0); r1 = fmaf(x1, e2[d+1], r1);
                    r2 = fmaf(x2, e2[d+2], r2); r3 = fmaf(x3, e2[d+3], r3);
                }
                float s1 = -2.f * (((p0 + p1) + (p2 + p3)) + en[c1]);
                float s2 = -2.f * (((r0 + r1) + (r2 + r3)) + en[c2]);
                if (s2 < s1 || (s2 == s1 && c2 < c1)) kmin = c2;
            }
            skm[row] = kmin;
        }
    }
    __syncthreads();

    // ---- epilogue: coalesced straight-through output + loss (exact fp32 q) ----
    float lsum = 0.f;
    const float* xg = x   + (size_t)rowBase * D;
    float*       og = out + (size_t)rowBase * D;
    #pragma unroll 4
    for (int j = 0; j < (BROWS * D) / TM; j++) {   // 32 iters
        int idx = j * TM + tid;
        int r = idx >> 6, d = idx & 63;
        float q  = g_eT[skm[r] * D + d];
        float xv = xg[idx];
        float t = q - xv;
        og[idx] = xv + t;
        lsum = fmaf(t, t, lsum);
    }
    #pragma unroll
    for (int o = 16; o > 0; o >>= 1) lsum += __shfl_xor_sync(0xffffffffu, lsum, o);
    if (lane == 0) red[w] = lsum;
    __syncthreads();
    if (tid == 0) {
        float s = red[0] + red[1] + red[2] + red[3];
        atomicAdd(&g_loss_sum, (double)s);
        __threadfence();
        int old = atomicAdd(&g_counter, 1);
        if (old == (int)gridDim.x - 1) {
            g_counter = 0;
            double l = atomicAdd(&g_loss_sum, 0.0);   // coherent read of final sum
            if (writeLoss)
                out[(size_t)Nrows * D] = (float)(2.0 * l / ((double)Nrows * (double)D));
        }
    }
}

extern "C" void kernel_launch(void* const* d_in, const int* in_sizes, int n_in,
                              void* d_out, int out_size) {
    const float* x = (const float*)d_in[0];
    const float* E = (const float*)d_in[1];
    float* out = (float*)d_out;
    const int N = in_sizes[0] / D;

    cudaFuncSetAttribute(vq_main_kernel, cudaFuncAttributeMaxDynamicSharedMemorySize, S_TOTAL);

    vq_prep_kernel<<<64, THREADS>>>(E);
    vq_main_kernel<<<N / BROWS, TM, S_TOTAL>>>(x, out, out_size > N * D ? 1 : 0, N);
}

// round 16
// speedup vs baseline: 1.3980x; 1.0549x over previous
#include <cuda_runtime.h>
#include <cuda_fp16.h>
#include <cstdint>

#define D        64
#define KC       512
#define BROWS    64
#define TM       128          // main-kernel threads (4 warps x 16 rows)
#define THREADS  256          // prep-kernel threads
#define DELTA    8.0e-3f
#define C_OFS    16.0f

// ---------------- device globals (scratch; allocs forbidden) ----------------
// E baked into mma-B-fragment order: [iter(64)][half(2)][lane(32)] uint4
__device__ __align__(16) uint4  g_efrag[64 * 2 * 32];
__device__ __align__(16) float  g_eT[KC * D];      // fp32 codebook [k][d] (transposed)
__device__ __align__(16) float  g_enormC2[KC];     // -(||e_k||^2 + C)/2
__device__ double g_loss_sum;
__device__ int    g_counter = 0;

// ---------------- smem layout (dynamic, main) ----------------
#define S_X      0                      // 64 * 128B (fp16, swizzled)   = 8192
#define S_EN     8192                   // 512 * 4B                     = 2048
#define S_KMIN   10240                  // 64 * 4B                      = 256
#define S_TOTAL  10496

__device__ __forceinline__ uint32_t smem_u32(const void* p) {
    uint32_t a;
    asm("{ .reg .u64 t; cvta.to.shared.u64 t, %1; cvt.u32.u64 %0, t; }" : "=r"(a) : "l"(p));
    return a;
}

__device__ __forceinline__ void cp_async16(uint32_t dst, const void* src) {
    asm volatile("cp.async.ca.shared.global [%0], [%1], 16;" :: "r"(dst), "l"(src));
}
__device__ __forceinline__ void cp_async_commit_wait() {
    asm volatile("cp.async.commit_group;");
    asm volatile("cp.async.wait_group 0;");
}

__device__ __forceinline__ void ldmatrix_x4(uint32_t* r, uint32_t addr) {
    asm volatile("ldmatrix.sync.aligned.m8n8.x4.shared.b16 {%0,%1,%2,%3}, [%4];"
                 : "=r"(r[0]), "=r"(r[1]), "=r"(r[2]), "=r"(r[3]) : "r"(addr));
}

__device__ __forceinline__ void mma16816(float& c0, float& c1, float& c2, float& c3,
                                         const uint32_t* a, uint32_t b0, uint32_t b1) {
    asm volatile("mma.sync.aligned.m16n8k16.row.col.f32.f16.f16.f32 "
                 "{%0,%1,%2,%3}, {%4,%5,%6,%7}, {%8,%9}, {%0,%1,%2,%3};"
                 : "+f"(c0), "+f"(c1), "+f"(c2), "+f"(c3)
                 : "r"(a[0]), "r"(a[1]), "r"(a[2]), "r"(a[3]), "r"(b0), "r"(b1));
}

// ================= fused prep: norms + fp32 transpose + B-fragment bake =================
__global__ void vq_prep_kernel(const float* __restrict__ E) {
    __shared__ float se[8][D + 1];     // [c_local][d], padded
    const int tid = threadIdx.x;
    const int c0  = blockIdx.x * 8;

    #pragma unroll
    for (int i = 0; i < 2; i++) {
        int t = i * THREADS + tid;     // 0..511
        int d = t >> 3, j = t & 7;     // E[d][c0+j]
        se[j][d] = E[d * KC + c0 + j];
    }
    __syncthreads();

    {
        int wj = tid >> 5, lane = tid & 31;
        float v = se[wj][lane];
        float u = se[wj][lane + 32];
        float s = v * v + u * u;
        #pragma unroll
        for (int o = 16; o > 0; o >>= 1) s += __shfl_xor_sync(0xffffffffu, s, o);
        if (lane == 0) g_enormC2[c0 + wj] = -0.5f * (s + C_OFS);
    }

    #pragma unroll
    for (int i = 0; i < 2; i++) {
        int t = i * THREADS + tid;
        int cl = t >> 6, d = t & 63;
        g_eT[(size_t)(c0 + cl) * D + d] = se[cl][d];
    }

    if (tid < 64) {
        int h = tid >> 5, lane = tid & 31;
        int cl = lane >> 2;
        int kd = 2 * (lane & 3);
        uint32_t r[4];
        #pragma unroll
        for (int i = 0; i < 2; i++) {
            int s = 2 * h + i;
            #pragma unroll
            for (int j = 0; j < 2; j++) {
                int d0 = s * 16 + j * 8 + kd;
                uint32_t lo = __half_as_ushort(__float2half_rn(se[cl][d0]));
                uint32_t hi = __half_as_ushort(__float2half_rn(se[cl][d0 + 1]));
                r[i * 2 + j] = lo | (hi << 16);
            }
        }
        g_efrag[(blockIdx.x * 2 + h) * 32 + lane] = make_uint4(r[0], r[1], r[2], r[3]);
    }
    if (blockIdx.x == 0 && tid == 0) g_loss_sum = 0.0;
}

// ================= main: 64-row tiles, 4 warps, cap 7 (single wave, 73-reg budget) =================
__global__ __launch_bounds__(TM, 7)
void vq_main_kernel(const float* __restrict__ x,
                    float* __restrict__ out,
                    int writeLoss, int Nrows) {
    extern __shared__ __align__(16) char sm[];
    const uint32_t sb = smem_u32(sm);
    __shared__ float red[4];

    const int tid  = threadIdx.x;
    const int w    = tid >> 5, lane = tid & 31;
    const int m4   = lane & 3,  q8  = lane >> 2;
    const int rowBase = blockIdx.x * BROWS;

    // ---- stage norms via cp.async (128 threads x 16B = 2048B) ----
    cp_async16(sb + S_EN + tid * 16, (const char*)g_enormC2 + tid * 16);
    // ---- stage X fp16 (swizzled rows of 128B) ----
    {
        const float4* xg = (const float4*)(x + (size_t)rowBase * D);
        #pragma unroll
        for (int i = 0; i < 8; i++) {
            int f = i * TM + tid;                 // float4 id, 0..1023
            float4 v = xg[f];
            int row = f >> 4, seg = f & 15;
            uint32_t h0 = __half_as_ushort(__float2half_rn(v.x));
            uint32_t h1 = __half_as_ushort(__float2half_rn(v.y));
            uint32_t h2 = __half_as_ushort(__float2half_rn(v.z));
            uint32_t h3 = __half_as_ushort(__float2half_rn(v.w));
            uint2 u = make_uint2(h0 | (h1 << 16), h2 | (h3 << 16));
            *(uint2*)(sm + S_X + row * 128 + ((seg * 8) ^ ((row & 7) << 4))) = u;
        }
    }
    cp_async_commit_wait();
    __syncthreads();

    // ---- preload A fragments: one m16 tile x 4 k-steps ----
    uint32_t afr[4][4];
    const int tb0 = w * 16;
    #pragma unroll
    for (int s = 0; s < 4; s++) {
        int row = tb0 + (lane & 15);
        uint32_t off = (uint32_t)(s * 32 + (lane >> 4) * 16) ^ (uint32_t)((row & 7) << 4);
        ldmatrix_x4(afr[s], sb + S_X + row * 128 + off);
    }

    // ---- sweep 512 codes; B fragments from L1-cached global; top-2 via
    //      raw-bit umin (a < 0 always => min score = min uint bits) ----
    uint32_t k1[2], k2[2];
    k1[0] = k1[1] = 0xFFFFFFFFu;
    k2[0] = k2[1] = 0xFFFFFFFFu;

    const uint4* __restrict__ fp = g_efrag + lane;

    #pragma unroll 8
    for (int n0 = 0; n0 < KC; n0 += 8) {
        uint4 u0 = __ldg(fp);
        uint4 u1 = __ldg(fp + 32);
        fp += 64;

        float2 en2 = *(const float2*)(sm + S_EN + (n0 + 2 * m4) * 4);
        const uint32_t col0 = (uint32_t)(n0 + 2 * m4), col1 = col0 + 1;

        float a0 = en2.x, a1 = en2.y, a2 = en2.x, a3 = en2.y;
        mma16816(a0, a1, a2, a3, afr[0], u0.x, u0.y);
        mma16816(a0, a1, a2, a3, afr[1], u0.z, u0.w);
        mma16816(a0, a1, a2, a3, afr[2], u1.x, u1.y);
        mma16816(a0, a1, a2, a3, afr[3], u1.z, u1.w);

        // rowA = tb0 + q8 (a0,a1) ; rowB = rowA + 8 (a2,a3)
        uint32_t key, mx;
        key = (__float_as_uint(a0) & 0xFFFFFE00u) | col0;
        mx = umax(k1[0], key); k1[0] = umin(k1[0], key); k2[0] = umin(k2[0], mx);
        key = (__float_as_uint(a1) & 0xFFFFFE00u) | col1;
        mx = umax(k1[0], key); k1[0] = umin(k1[0], key); k2[0] = umin(k2[0], mx);
        key = (__float_as_uint(a2) & 0xFFFFFE00u) | col0;
        mx = umax(k1[1], key); k1[1] = umin(k1[1], key); k2[1] = umin(k2[1], mx);
        key = (__float_as_uint(a3) & 0xFFFFFE00u) | col1;
        mx = umax(k1[1], key); k1[1] = umin(k1[1], key); k2[1] = umin(k2[1], mx);
    }

    // ---- merge top-2 across the 4 lanes sharing each row ----
    #pragma unroll
    for (int i = 0; i < 2; i++) {
        #pragma unroll
        for (int off = 1; off <= 2; off <<= 1) {
            uint32_t o1 = __shfl_xor_sync(0xffffffffu, k1[i], off);
            uint32_t o2 = __shfl_xor_sync(0xffffffffu, k2[i], off);
            uint32_t mx = umax(k1[i], o1);
            k1[i] = umin(k1[i], o1);
            k2[i] = umin(umin(k2[i], o2), mx);
        }
    }

    // ---- finalize rows: certified refinement on narrow gaps ----
    int* skm = (int*)(sm + S_KMIN);
    if (m4 == 0) {
        const float* en = (const float*)(sm + S_EN);
        #pragma unroll
        for (int i = 0; i < 2; i++) {
            int row = tb0 + q8 + i * 8;
            int c1 = (int)(k1[i] & 511u), c2 = (int)(k2[i] & 511u);
            float f1 = __uint_as_float(k1[i] & 0xFFFFFE00u);   // best (largest a)
            float f2 = __uint_as_float(k2[i] & 0xFFFFFE00u);
            int kmin = c1;
            if (2.f * (f1 - f2) < DELTA) {
                const float* xr = x + (size_t)(rowBase + row) * D;
                const float* e1 = g_eT + c1 * D;
                const float* e2 = g_eT + c2 * D;
                float p0 = 0.f, p1 = 0.f, p2 = 0.f, p3 = 0.f;
                float r0 = 0.f, r1 = 0.f, r2 = 0.f, r3 = 0.f;
                #pragma unroll
                for (int d = 0; d < D; d += 4) {
                    float x0 = xr[d], x1 = xr[d+1], x2 = xr[d+2], x3 = xr[d+3];
                    p0 = fmaf(x0, e1[d],   p0); p1 = fmaf(x1, e1[d+1], p1);
                    p2 = fmaf(x2, e1[d+2], p2); p3 = fmaf(x3, e1[d+3], p3);
                    r0 = fmaf(x0, e2[d],   r0); r1 = fmaf(x1, e2[d+1], r1);
                    r2 = fmaf(x2, e2[d+2], r2); r3 = fmaf(x3, e2[d+3], r3);
                }
                float s1 = -2.f * (((p0 + p1) + (p2 + p3)) + en[c1]);
                float s2 = -2.f * (((r0 + r1) + (r2 + r3)) + en[c2]);
                if (s2 < s1 || (s2 == s1 && c2 < c1)) kmin = c2;
            }
            skm[row] = kmin;
        }
    }
    __syncthreads();

    // ---- epilogue: coalesced straight-through output + loss (exact fp32 q) ----
    float lsum = 0.f;
    const float* xg = x   + (size_t)rowBase * D;
    float*       og = out + (size_t)rowBase * D;
    #pragma unroll 4
    for (int j = 0; j < (BROWS * D) / TM; j++) {   // 32 iters
        int idx = j * TM + tid;
        int r = idx >> 6, d = idx & 63;
        float q  = g_eT[skm[r] * D + d];
        float xv = xg[idx];
        float t = q - xv;
        og[idx] = xv + t;
        lsum = fmaf(t, t, lsum);
    }
    #pragma unroll
    for (int o = 16; o > 0; o >>= 1) lsum += __shfl_xor_sync(0xffffffffu, lsum, o);
    if (lane == 0) red[w] = lsum;
    __syncthreads();
    if (tid == 0) {
        float s = red[0] + red[1] + red[2] + red[3];
        atomicAdd(&g_loss_sum, (double)s);
        __threadfence();
        int old = atomicAdd(&g_counter, 1);
        if (old == (int)gridDim.x - 1) {
            g_counter = 0;
            double l = atomicAdd(&g_loss_sum, 0.0);   // coherent read of final sum
            if (writeLoss)
                out[(size_t)Nrows * D] = (float)(2.0 * l / ((double)Nrows * (double)D));
        }
    }
}

extern "C" void kernel_launch(void* const* d_in, const int* in_sizes, int n_in,
                              void* d_out, int out_size) {
    const float* x = (const float*)d_in[0];
    const float* E = (const float*)d_in[1];
    float* out = (float*)d_out;
    const int N = in_sizes[0] / D;

    cudaFuncSetAttribute(vq_main_kernel, cudaFuncAttributeMaxDynamicSharedMemorySize, S_TOTAL);

    vq_prep_kernel<<<64, THREADS>>>(E);
    vq_main_kernel<<<N / BROWS, TM, S_TOTAL>>>(x, out, out_size > N * D ? 1 : 0, N);
}

// round 17
// speedup vs baseline: 1.4951x; 1.0695x over previous
#include <cuda_runtime.h>
#include <cuda_fp16.h>
#include <cstdint>

#define D        64
#define KC       512
#define BROWS    64
#define TM       128          // main-kernel threads (4 warps x 16 rows)
#define THREADS  256          // prep-kernel threads
#define DELTA    8.0e-3f
#define C_OFS    16.0f
#define KINIT    -3.402823466e38f   // most negative finite float

// ---------------- device globals (scratch; allocs forbidden) ----------------
// E baked into mma-B-fragment order: [iter(64)][half(2)][lane(32)] uint4
__device__ __align__(16) uint4  g_efrag[64 * 2 * 32];
__device__ __align__(16) float  g_eT[KC * D];      // fp32 codebook [k][d] (transposed)
__device__ __align__(16) float  g_enormC2[KC];     // -(||e_k||^2 + C)/2
__device__ double g_loss_sum;
__device__ int    g_counter = 0;

// ---------------- smem layout (dynamic, main) ----------------
#define S_X      0                      // 64 * 128B (fp16, swizzled)   = 8192
#define S_EN     8192                   // 512 * 4B                     = 2048
#define S_KMIN   10240                  // 64 * 4B                      = 256
#define S_TOTAL  10496

__device__ __forceinline__ uint32_t smem_u32(const void* p) {
    uint32_t a;
    asm("{ .reg .u64 t; cvta.to.shared.u64 t, %1; cvt.u32.u64 %0, t; }" : "=r"(a) : "l"(p));
    return a;
}

__device__ __forceinline__ void cp_async16(uint32_t dst, const void* src) {
    asm volatile("cp.async.ca.shared.global [%0], [%1], 16;" :: "r"(dst), "l"(src));
}
__device__ __forceinline__ void cp_async_commit_wait() {
    asm volatile("cp.async.commit_group;");
    asm volatile("cp.async.wait_group 0;");
}

__device__ __forceinline__ void ldmatrix_x4(uint32_t* r, uint32_t addr) {
    asm volatile("ldmatrix.sync.aligned.m8n8.x4.shared.b16 {%0,%1,%2,%3}, [%4];"
                 : "=r"(r[0]), "=r"(r[1]), "=r"(r[2]), "=r"(r[3]) : "r"(addr));
}

__device__ __forceinline__ void mma16816(float& c0, float& c1, float& c2, float& c3,
                                         const uint32_t* a, uint32_t b0, uint32_t b1) {
    asm volatile("mma.sync.aligned.m16n8k16.row.col.f32.f16.f16.f32 "
                 "{%0,%1,%2,%3}, {%4,%5,%6,%7}, {%8,%9}, {%0,%1,%2,%3};"
                 : "+f"(c0), "+f"(c1), "+f"(c2), "+f"(c3)
                 : "r"(a[0]), "r"(a[1]), "r"(a[2]), "r"(a[3]), "r"(b0), "r"(b1));
}

// pack two fp32 into fp16x2 with one instruction
__device__ __forceinline__ uint32_t f22h2(float lo, float hi) {
    uint32_t r;
    asm("cvt.rn.f16x2.f32 %0, %1, %2;" : "=r"(r) : "f"(hi), "f"(lo));
    return r;
}

// key: (score_bits & ~511) | col, interpreted as float. All scores negative =>
// min bits == max float, FMNMX is a select so col bits survive, no NaNs arise.
__device__ __forceinline__ float mkkey(float a, uint32_t col) {
    return __uint_as_float((__float_as_uint(a) & 0xFFFFFE00u) | col);
}

// ================= fused prep: norms + fp32 transpose + B-fragment bake =================
__global__ void vq_prep_kernel(const float* __restrict__ E) {
    __shared__ float se[8][D + 1];     // [c_local][d], padded
    const int tid = threadIdx.x;
    const int c0  = blockIdx.x * 8;

    #pragma unroll
    for (int i = 0; i < 2; i++) {
        int t = i * THREADS + tid;     // 0..511
        int d = t >> 3, j = t & 7;     // E[d][c0+j]
        se[j][d] = E[d * KC + c0 + j];
    }
    __syncthreads();

    {
        int wj = tid >> 5, lane = tid & 31;
        float v = se[wj][lane];
        float u = se[wj][lane + 32];
        float s = v * v + u * u;
        #pragma unroll
        for (int o = 16; o > 0; o >>= 1) s += __shfl_xor_sync(0xffffffffu, s, o);
        if (lane == 0) g_enormC2[c0 + wj] = -0.5f * (s + C_OFS);
    }

    #pragma unroll
    for (int i = 0; i < 2; i++) {
        int t = i * THREADS + tid;
        int cl = t >> 6, d = t & 63;
        g_eT[(size_t)(c0 + cl) * D + d] = se[cl][d];
    }

    if (tid < 64) {
        int h = tid >> 5, lane = tid & 31;
        int cl = lane >> 2;
        int kd = 2 * (lane & 3);
        uint32_t r[4];
        #pragma unroll
        for (int i = 0; i < 2; i++) {
            int s = 2 * h + i;
            #pragma unroll
            for (int j = 0; j < 2; j++) {
                int d0 = s * 16 + j * 8 + kd;
                uint32_t lo = __half_as_ushort(__float2half_rn(se[cl][d0]));
                uint32_t hi = __half_as_ushort(__float2half_rn(se[cl][d0 + 1]));
                r[i * 2 + j] = lo | (hi << 16);
            }
        }
        g_efrag[(blockIdx.x * 2 + h) * 32 + lane] = make_uint4(r[0], r[1], r[2], r[3]);
    }
    if (blockIdx.x == 0 && tid == 0) g_loss_sum = 0.0;
}

// ================= main: 64-row tiles, 4 warps, cap 7 (single wave) =================
__global__ __launch_bounds__(TM, 7)
void vq_main_kernel(const float* __restrict__ x,
                    float* __restrict__ out,
                    int writeLoss, int Nrows) {
    extern __shared__ __align__(16) char sm[];
    const uint32_t sb = smem_u32(sm);
    __shared__ float red[4];

    const int tid  = threadIdx.x;
    const int w    = tid >> 5, lane = tid & 31;
    const int m4   = lane & 3,  q8  = lane >> 2;
    const int rowBase = blockIdx.x * BROWS;

    // ---- stage norms via cp.async (128 threads x 16B = 2048B) ----
    cp_async16(sb + S_EN + tid * 16, (const char*)g_enormC2 + tid * 16);
    // ---- stage X fp16 (swizzled rows of 128B; packed converts) ----
    {
        const float4* xg = (const float4*)(x + (size_t)rowBase * D);
        #pragma unroll
        for (int i = 0; i < 8; i++) {
            int f = i * TM + tid;                 // float4 id, 0..1023
            float4 v = xg[f];
            int row = f >> 4, seg = f & 15;
            uint2 u = make_uint2(f22h2(v.x, v.y), f22h2(v.z, v.w));
            *(uint2*)(sm + S_X + row * 128 + ((seg * 8) ^ ((row & 7) << 4))) = u;
        }
    }
    cp_async_commit_wait();
    __syncthreads();

    // ---- preload A fragments: one m16 tile x 4 k-steps ----
    uint32_t afr[4][4];
    const int tb0 = w * 16;
    #pragma unroll
    for (int s = 0; s < 4; s++) {
        int row = tb0 + (lane & 15);
        uint32_t off = (uint32_t)(s * 32 + (lane >> 4) * 16) ^ (uint32_t)((row & 7) << 4);
        ldmatrix_x4(afr[s], sb + S_X + row * 128 + off);
    }

    // ---- sweep 512 codes; top-2 via FMNMX on packed float keys
    //      (max float == min bits == min score; FMA pipe, ALU relieved) ----
    float k1[2], k2[2];
    k1[0] = k1[1] = KINIT;
    k2[0] = k2[1] = KINIT;

    const uint4* __restrict__ fp = g_efrag + lane;

    #pragma unroll 8
    for (int n0 = 0; n0 < KC; n0 += 8) {
        uint4 u0 = __ldg(fp);
        uint4 u1 = __ldg(fp + 32);
        fp += 64;

        float2 en2 = *(const float2*)(sm + S_EN + (n0 + 2 * m4) * 4);
        const uint32_t col0 = (uint32_t)(n0 + 2 * m4), col1 = col0 + 1;

        float a0 = en2.x, a1 = en2.y, a2 = en2.x, a3 = en2.y;
        mma16816(a0, a1, a2, a3, afr[0], u0.x, u0.y);
        mma16816(a0, a1, a2, a3, afr[1], u0.z, u0.w);
        mma16816(a0, a1, a2, a3, afr[2], u1.x, u1.y);
        mma16816(a0, a1, a2, a3, afr[3], u1.z, u1.w);

        // rowA = tb0 + q8 (a0,a1) ; rowB = rowA + 8 (a2,a3)
        float key, mx;
        key = mkkey(a0, col0);
        mx = fminf(k1[0], key); k1[0] = fmaxf(k1[0], key); k2[0] = fmaxf(k2[0], mx);
        key = mkkey(a1, col1);
        mx = fminf(k1[0], key); k1[0] = fmaxf(k1[0], key); k2[0] = fmaxf(k2[0], mx);
        key = mkkey(a2, col0);
        mx = fminf(k1[1], key); k1[1] = fmaxf(k1[1], key); k2[1] = fmaxf(k2[1], mx);
        key = mkkey(a3, col1);
        mx = fminf(k1[1], key); k1[1] = fmaxf(k1[1], key); k2[1] = fmaxf(k2[1], mx);
    }

    // ---- merge top-2 across the 4 lanes sharing each row ----
    #pragma unroll
    for (int i = 0; i < 2; i++) {
        #pragma unroll
        for (int off = 1; off <= 2; off <<= 1) {
            float o1 = __shfl_xor_sync(0xffffffffu, k1[i], off);
            float o2 = __shfl_xor_sync(0xffffffffu, k2[i], off);
            float mx = fminf(k1[i], o1);
            k1[i] = fmaxf(k1[i], o1);
            k2[i] = fmaxf(fmaxf(k2[i], o2), mx);
        }
    }

    // ---- finalize rows: certified refinement on narrow gaps ----
    int* skm = (int*)(sm + S_KMIN);
    if (m4 == 0) {
        const float* en = (const float*)(sm + S_EN);
        #pragma unroll
        for (int i = 0; i < 2; i++) {
            int row = tb0 + q8 + i * 8;
            uint32_t b1 = __float_as_uint(k1[i]), b2 = __float_as_uint(k2[i]);
            int c1 = (int)(b1 & 511u), c2 = (int)(b2 & 511u);
            float f1 = __uint_as_float(b1 & 0xFFFFFE00u);   // best (largest a)
            float f2 = __uint_as_float(b2 & 0xFFFFFE00u);
            int kmin = c1;
            if (2.f * (f1 - f2) < DELTA) {
                const float* xr = x + (size_t)(rowBase + row) * D;
                const float* e1 = g_eT + c1 * D;
                const float* e2 = g_eT + c2 * D;
                float p0 = 0.f, p1 = 0.f, p2 = 0.f, p3 = 0.f;
                float r0 = 0.f, r1 = 0.f, r2 = 0.f, r3 = 0.f;
                #pragma unroll
                for (int d = 0; d < D; d += 4) {
                    float x0 = xr[d], x1 = xr[d+1], x2 = xr[d+2], x3 = xr[d+3];
                    p0 = fmaf(x0, e1[d],   p0); p1 = fmaf(x1, e1[d+1], p1);
                    p2 = fmaf(x2, e1[d+2], p2); p3 = fmaf(x3, e1[d+3], p3);
                    r0 = fmaf(x0, e2[d],   r0); r1 = fmaf(x1, e2[d+1], r1);
                    r2 = fmaf(x2, e2[d+2], r2); r3 = fmaf(x3, e2[d+3], r3);
                }
                float s1 = -2.f * (((p0 + p1) + (p2 + p3)) + en[c1]);
                float s2 = -2.f * (((r0 + r1) + (r2 + r3)) + en[c2]);
                if (s2 < s1 || (s2 == s1 && c2 < c1)) kmin = c2;
            }
            skm[row] = kmin;
        }
    }
    __syncthreads();

    // ---- epilogue: float4-vectorized straight-through output + loss ----
    float lsum = 0.f;
    const float4* xg4 = (const float4*)(x   + (size_t)rowBase * D);
    float4*       og4 = (float4*)      (out + (size_t)rowBase * D);
    #pragma unroll 4
    for (int j = 0; j < (BROWS * D) / (TM * 4); j++) {   // 8 iters
        int idx = j * TM + tid;              // float4 id, 0..511
        int r = idx >> 4;
        const float4* qe = (const float4*)(g_eT + (size_t)skm[r] * D) + (idx & 15);
        float4 q = *qe;
        float4 xv = xg4[idx];
        float t0 = q.x - xv.x, t1 = q.y - xv.y, t2 = q.z - xv.z, t3 = q.w - xv.w;
        og4[idx] = make_float4(xv.x + t0, xv.y + t1, xv.z + t2, xv.w + t3);
        lsum = fmaf(t0, t0, lsum);
        lsum = fmaf(t1, t1, lsum);
        lsum = fmaf(t2, t2, lsum);
        lsum = fmaf(t3, t3, lsum);
    }
    #pragma unroll
    for (int o = 16; o > 0; o >>= 1) lsum += __shfl_xor_sync(0xffffffffu, lsum, o);
    if (lane == 0) red[w] = lsum;
    __syncthreads();
    if (tid == 0) {
        float s = red[0] + red[1] + red[2] + red[3];
        atomicAdd(&g_loss_sum, (double)s);
        __threadfence();
        int old = atomicAdd(&g_counter, 1);
        if (old == (int)gridDim.x - 1) {
            g_counter = 0;
            double l = atomicAdd(&g_loss_sum, 0.0);   // coherent read of final sum
            if (writeLoss)
                out[(size_t)Nrows * D] = (float)(2.0 * l / ((double)Nrows * (double)D));
        }
    }
}

extern "C" void kernel_launch(void* const* d_in, const int* in_sizes, int n_in,
                              void* d_out, int out_size) {
    const float* x = (const float*)d_in[0];
    const float* E = (const float*)d_in[1];
    float* out = (float*)d_out;
    const int N = in_sizes[0] / D;

    cudaFuncSetAttribute(vq_main_kernel, cudaFuncAttributeMaxDynamicSharedMemorySize, S_TOTAL);

    vq_prep_kernel<<<64, THREADS>>>(E);
    vq_main_kernel<<<N / BROWS, TM, S_TOTAL>>>(x, out, out_size > N * D ? 1 : 0, N);
}